// round 1
// baseline (speedup 1.0000x reference)
#include <cuda_runtime.h>
#include <math.h>

// Problem constants
#define NBATCH 2
#define L_SEQ 2048
#define D_MODEL 1024
#define H_HEADS 16
#define DH 64
#define QKV_STRIDE 3072          // 3*D per row of qkv
#define NH_TOT (NBATCH * H_HEADS)
#define OUT_ELEMS (NBATCH * L_SEQ * D_MODEL)   // 4194304

// Scratch (static device memory — no allocations anywhere)
__device__ float g_qkv[(size_t)NBATCH * L_SEQ * QKV_STRIDE];   // 50.3 MB
__device__ float g_qs[NH_TOT * DH];                            // scaled q_rel
__device__ float g_wn[NH_TOT * L_SEQ];                         // normalized Toeplitz kernel
__device__ float g_merged[(size_t)NBATCH * L_SEQ * D_MODEL];   // 33.5 MB

// ---------------------------------------------------------------------------
// Tiled SGEMM: C[m,n] = sum_k A[m,k] * B[n,k] + bias[n]
// 128x128 tile, BK=16, 256 threads, 8x8 microtile (split 4+4 to avoid bank
// conflicts), float4 global loads, transposed smem staging.
// Requires M%128==0, N%128==0, K%16==0 (true for all calls here).
// ---------------------------------------------------------------------------
__global__ __launch_bounds__(256)
void gemm_bias_kernel(const float* __restrict__ A, const float* __restrict__ B,
                      const float* __restrict__ bias, float* __restrict__ C,
                      int M, int N, int K)
{
    __shared__ float As[16][132];
    __shared__ float Bs[16][132];
    const int tid = threadIdx.x;
    const int bm = blockIdx.y * 128;
    const int bn = blockIdx.x * 128;
    const int tx = tid & 15;
    const int ty = tid >> 4;
    const int lrow = tid >> 2;          // 0..63
    const int lcol = (tid & 3) << 2;    // 0,4,8,12

    float acc[8][8];
#pragma unroll
    for (int i = 0; i < 8; i++)
#pragma unroll
        for (int j = 0; j < 8; j++) acc[i][j] = 0.f;

    const float* Ab = A + (size_t)bm * K;
    const float* Bb = B + (size_t)bn * K;

    for (int k0 = 0; k0 < K; k0 += 16) {
#pragma unroll
        for (int r = 0; r < 2; r++) {
            int row = lrow + r * 64;
            float4 va = *(const float4*)(Ab + (size_t)row * K + k0 + lcol);
            As[lcol + 0][row] = va.x; As[lcol + 1][row] = va.y;
            As[lcol + 2][row] = va.z; As[lcol + 3][row] = va.w;
            float4 vb = *(const float4*)(Bb + (size_t)row * K + k0 + lcol);
            Bs[lcol + 0][row] = vb.x; Bs[lcol + 1][row] = vb.y;
            Bs[lcol + 2][row] = vb.z; Bs[lcol + 3][row] = vb.w;
        }
        __syncthreads();
#pragma unroll
        for (int k = 0; k < 16; k++) {
            float ra[8], rb[8];
            *(float4*)&ra[0] = *(const float4*)&As[k][ty * 4];
            *(float4*)&ra[4] = *(const float4*)&As[k][64 + ty * 4];
            *(float4*)&rb[0] = *(const float4*)&Bs[k][tx * 4];
            *(float4*)&rb[4] = *(const float4*)&Bs[k][64 + tx * 4];
#pragma unroll
            for (int i = 0; i < 8; i++)
#pragma unroll
                for (int j = 0; j < 8; j++)
                    acc[i][j] = fmaf(ra[i], rb[j], acc[i][j]);
        }
        __syncthreads();
    }

#pragma unroll
    for (int i = 0; i < 8; i++) {
        int row = bm + ((i < 4) ? (ty * 4 + i) : (64 + ty * 4 + i - 4));
#pragma unroll
        for (int jj = 0; jj < 2; jj++) {
            int col = bn + ((jj == 0) ? (tx * 4) : (64 + tx * 4));
            float4 b4 = *(const float4*)(bias + col);
            float4 o;
            o.x = acc[i][jj * 4 + 0] + b4.x;
            o.y = acc[i][jj * 4 + 1] + b4.y;
            o.z = acc[i][jj * 4 + 2] + b4.z;
            o.w = acc[i][jj * 4 + 3] + b4.w;
            *(float4*)(C + (size_t)row * N + col) = o;
        }
    }
}

// ---------------------------------------------------------------------------
// Fused conv(kt=3) -> exact GELU -> LayerNorm(DH) -> mean over L  =>  q_rel.
// ln output is never needed downstream, only its mean over L.
// One block per head (nh). 512 threads = 16 warps; warp w handles
// t = w, w+16, ... Each lane owns channels d and d+32.
// Deterministic: warp shuffles + fixed-order shared reduction (no atomics).
// Output g_qs already folds scaling (DH^-0.5) and the 1/L mean.
// ---------------------------------------------------------------------------
__global__ __launch_bounds__(512)
void conv_ln_qrel_kernel(const float* __restrict__ conv_w, const float* __restrict__ conv_b,
                         const float* __restrict__ ln_g, const float* __restrict__ ln_b)
{
    const int nh = blockIdx.x;
    const int n = nh >> 4, h = nh & 15;
    const int tid = threadIdx.x;
    const int w = tid >> 5, lane = tid & 31;
    const int d0 = lane, d1 = lane + 32;
    const float* qbase = g_qkv + (size_t)n * L_SEQ * QKV_STRIDE + h * DH;

    const float cw00 = conv_w[d0 * 3 + 0], cw01 = conv_w[d0 * 3 + 1], cw02 = conv_w[d0 * 3 + 2];
    const float cw10 = conv_w[d1 * 3 + 0], cw11 = conv_w[d1 * 3 + 1], cw12 = conv_w[d1 * 3 + 2];
    const float cb0 = conv_b[d0], cb1 = conv_b[d1];
    const float lg0 = ln_g[d0], lb0 = ln_b[d0];
    const float lg1 = ln_g[d1], lb1 = ln_b[d1];

    float p0 = 0.f, p1 = 0.f;
    for (int t = w; t < L_SEQ; t += 16) {
        float c0 = cb0, c1 = cb1;
        {
            const float* r = qbase + (size_t)t * QKV_STRIDE;
            c0 = fmaf(r[d0], cw02, c0); c1 = fmaf(r[d1], cw12, c1);
        }
        if (t >= 1) {
            const float* r = qbase + (size_t)(t - 1) * QKV_STRIDE;
            c0 = fmaf(r[d0], cw01, c0); c1 = fmaf(r[d1], cw11, c1);
        }
        if (t >= 2) {
            const float* r = qbase + (size_t)(t - 2) * QKV_STRIDE;
            c0 = fmaf(r[d0], cw00, c0); c1 = fmaf(r[d1], cw10, c1);
        }
        // exact GELU: 0.5*x*(1+erf(x/sqrt(2)))
        float g0 = 0.5f * c0 * (1.f + erff(c0 * 0.70710678118654752f));
        float g1 = 0.5f * c1 * (1.f + erff(c1 * 0.70710678118654752f));
        float s = g0 + g1, sq = g0 * g0 + g1 * g1;
#pragma unroll
        for (int o = 16; o; o >>= 1) {
            s  += __shfl_xor_sync(0xffffffffu, s,  o);
            sq += __shfl_xor_sync(0xffffffffu, sq, o);
        }
        float mu = s * (1.f / 64.f);
        float var = sq * (1.f / 64.f) - mu * mu;
        float rs = rsqrtf(var + 1e-5f);
        p0 += (g0 - mu) * rs * lg0 + lb0;
        p1 += (g1 - mu) * rs * lg1 + lb1;
    }

    __shared__ float part[16][64];
    part[w][d0] = p0;
    part[w][d1] = p1;
    __syncthreads();
    if (tid < 64) {
        float s = 0.f;
#pragma unroll
        for (int i = 0; i < 16; i++) s += part[i][tid];
        // fold scaling = DH^-0.5 = 0.125 and mean /L
        g_qs[nh * 64 + tid] = s * (0.125f / 2048.f);
    }
}

// ---------------------------------------------------------------------------
// Wk[nh,l] = sum_d g_qs[nh,d] * k[nh,l,d] ; Wn = Wk / (sum_l |Wk| + 1e-6).
// One block per head; 256 threads x 8 l's each; deterministic block reduce.
// ---------------------------------------------------------------------------
__global__ __launch_bounds__(256)
void wk_kernel()
{
    const int nh = blockIdx.x;
    const int n = nh >> 4, h = nh & 15;
    const int tid = threadIdx.x;
    __shared__ float4 qs4[16];
    if (tid < 16) qs4[tid] = ((const float4*)(g_qs + nh * 64))[tid];
    __syncthreads();

    const float* kbase = g_qkv + (size_t)n * L_SEQ * QKV_STRIDE + D_MODEL + h * DH;
    float wk[8];
    float la = 0.f;
#pragma unroll
    for (int i = 0; i < 8; i++) {
        int l = tid + i * 256;
        const float4* kr = (const float4*)(kbase + (size_t)l * QKV_STRIDE);
        float a = 0.f;
#pragma unroll
        for (int d4 = 0; d4 < 16; d4++) {
            float4 kv = kr[d4]; float4 q = qs4[d4];
            a = fmaf(q.x, kv.x, a); a = fmaf(q.y, kv.y, a);
            a = fmaf(q.z, kv.z, a); a = fmaf(q.w, kv.w, a);
        }
        wk[i] = a;
        la += fabsf(a);
    }
    __shared__ float red[256];
    red[tid] = la;
    __syncthreads();
    for (int o = 128; o; o >>= 1) {
        if (tid < o) red[tid] += red[tid + o];
        __syncthreads();
    }
    const float scale = 1.f / (red[0] + 1e-6f);
#pragma unroll
    for (int i = 0; i < 8; i++)
        g_wn[nh * L_SEQ + tid + i * 256] = wk[i] * scale;
}

// ---------------------------------------------------------------------------
// attn[nh,t,d] = sum_{s<=t} Wn[nh, t-s] * v[nh,s,d]   (causal Toeplitz matmul)
// Tile 64 t-rows x 64 d-cols per block, s in 64-chunks; skip tiles above the
// diagonal. Writes directly into merged (N,L,D) layout.
// ---------------------------------------------------------------------------
__global__ __launch_bounds__(256)
void attn_kernel()
{
    const int t_tile = blockIdx.x;         // 0..31
    const int nh = blockIdx.y;             // 0..31
    const int n = nh >> 4, h = nh & 15;
    const int tid = threadIdx.x;
    const int tx = tid & 15, ty = tid >> 4;
    const int t0 = t_tile * 64;

    __shared__ float w_sh[128];
    __shared__ float Vs[64][64];

    float acc[4][4];
#pragma unroll
    for (int i = 0; i < 4; i++)
#pragma unroll
        for (int j = 0; j < 4; j++) acc[i][j] = 0.f;

    const float* vbase = g_qkv + (size_t)n * L_SEQ * QKV_STRIDE + 2 * D_MODEL + h * DH;
    const float* wn = g_wn + nh * L_SEQ;

    for (int s0 = 0; s0 <= t0; s0 += 64) {
        if (tid < 128) {
            int lag = t0 - s0 - 63 + tid;
            w_sh[tid] = (lag >= 0) ? wn[lag] : 0.f;
        }
#pragma unroll
        for (int it = 0; it < 4; it++) {
            int row = (tid >> 4) + it * 16;
            int col = (tid & 15) * 4;
            float4 v = *(const float4*)(vbase + (size_t)(s0 + row) * QKV_STRIDE + col);
            *(float4*)&Vs[row][col] = v;
        }
        __syncthreads();
#pragma unroll 8
        for (int s = 0; s < 64; s++) {
            float4 v4 = *(const float4*)&Vs[s][tx * 4];
            int base = ty * 4 + 63 - s;
#pragma unroll
            for (int i = 0; i < 4; i++) {
                float wv = w_sh[base + i];
                acc[i][0] = fmaf(wv, v4.x, acc[i][0]);
                acc[i][1] = fmaf(wv, v4.y, acc[i][1]);
                acc[i][2] = fmaf(wv, v4.z, acc[i][2]);
                acc[i][3] = fmaf(wv, v4.w, acc[i][3]);
            }
        }
        __syncthreads();
    }

    float* mbase = g_merged + (size_t)n * L_SEQ * D_MODEL + h * DH;
#pragma unroll
    for (int i = 0; i < 4; i++) {
        int t = t0 + ty * 4 + i;
        float4 o = make_float4(acc[i][0], acc[i][1], acc[i][2], acc[i][3]);
        *(float4*)(mbase + (size_t)t * D_MODEL + tx * 4) = o;
    }
}

__global__ void fill_kernel(float* p, int nfill, float v)
{
    int i = blockIdx.x * blockDim.x + threadIdx.x;
    if (i < nfill) p[i] = v;
}

// ---------------------------------------------------------------------------
extern "C" void kernel_launch(void* const* d_in, const int* in_sizes, int n_in,
                              void* d_out, int out_size)
{
    const float* x       = (const float*)d_in[0];
    const float* in_w    = (const float*)d_in[1];
    const float* in_b    = (const float*)d_in[2];
    const float* conv_w  = (const float*)d_in[3];
    const float* conv_b  = (const float*)d_in[4];
    const float* ln_g    = (const float*)d_in[5];
    const float* ln_b    = (const float*)d_in[6];
    const float* out_w   = (const float*)d_in[7];
    const float* out_b   = (const float*)d_in[8];
    float* out = (float*)d_out;

    void* pq = nullptr; cudaGetSymbolAddress(&pq, g_qkv);
    void* pm = nullptr; cudaGetSymbolAddress(&pm, g_merged);
    float* qkv    = (float*)pq;
    float* merged = (float*)pm;

    // 1) qkv = x @ in_proj_w^T + in_proj_b     (4096 x 3072, K=1024)
    gemm_bias_kernel<<<dim3(3072 / 128, 4096 / 128), 256>>>(x, in_w, in_b, qkv,
                                                            NBATCH * L_SEQ, 3 * D_MODEL, D_MODEL);
    // 2) fused conv -> gelu -> LN -> mean_L  => q_rel (with scaling & 1/L folded)
    conv_ln_qrel_kernel<<<NH_TOT, 512>>>(conv_w, conv_b, ln_g, ln_b);
    // 3) Wk + L1 normalization => Wn
    wk_kernel<<<NH_TOT, 256>>>();
    // 4) causal Toeplitz attention => merged
    attn_kernel<<<dim3(L_SEQ / 64, NH_TOT), 256>>>();
    // 5) output = merged @ out_w^T + out_b
    gemm_bias_kernel<<<dim3(D_MODEL / 128, 4096 / 128), 256>>>(merged, out_w, out_b, out,
                                                               NBATCH * L_SEQ, D_MODEL, D_MODEL);
    // 6) mock attention weights = 1/L appended after the main output
    int nmock = out_size - OUT_ELEMS;
    if (nmock > 0)
        fill_kernel<<<(nmock + 255) / 256, 256>>>(out + OUT_ELEMS, nmock, 1.0f / (float)L_SEQ);
}

// round 3
// speedup vs baseline: 1.6493x; 1.6493x over previous
#include <cuda_runtime.h>
#include <cuda_bf16.h>
#include <math.h>
#include <stdint.h>

// Problem constants
#define NBATCH 2
#define L_SEQ 2048
#define D_MODEL 1024
#define H_HEADS 16
#define DH 64
#define QKV_STRIDE 3072
#define NH_TOT (NBATCH * H_HEADS)
#define OUT_ELEMS (NBATCH * L_SEQ * D_MODEL)
#define GK 1024
#define GKC 32                    // K chunks of 32
// smem: 3 stages x 4 matrices x 128 rows x 80B
#define ROW_B 80
#define MAT_B (128 * ROW_B)       // 10240
#define STG_B (4 * MAT_B)         // 40960
#define GT_SMEM (3 * STG_B)       // 122880

// Static device scratch (no allocations anywhere)
__device__ float g_qkv[(size_t)NBATCH * L_SEQ * QKV_STRIDE];
__device__ float g_qs[NH_TOT * DH];
__device__ float g_wn[NH_TOT * L_SEQ];
__device__ float g_merged[(size_t)NBATCH * L_SEQ * D_MODEL];
__device__ __align__(16) __nv_bfloat16 g_ah[(size_t)4096 * 1024];
__device__ __align__(16) __nv_bfloat16 g_al[(size_t)4096 * 1024];
__device__ __align__(16) __nv_bfloat16 g_bh[(size_t)3072 * 1024];
__device__ __align__(16) __nv_bfloat16 g_bl[(size_t)3072 * 1024];

// ---------------------------------------------------------------------------
__device__ __forceinline__ uint32_t smem_u32(const void* p) {
    uint32_t a;
    asm("{ .reg .u64 t; cvta.to.shared.u64 t, %1; cvt.u32.u64 %0, t; }" : "=r"(a) : "l"(p));
    return a;
}

#define CP_ASYNC16(dst, src) \
    asm volatile("cp.async.cg.shared.global [%0], [%1], 16;" :: "r"(dst), "l"(src))
#define CP_COMMIT() asm volatile("cp.async.commit_group;" ::: "memory")
#define CP_WAIT1()  asm volatile("cp.async.wait_group 1;" ::: "memory")

#define LDSM_X4(r, addr) \
    asm volatile("ldmatrix.sync.aligned.m8n8.x4.shared.b16 {%0,%1,%2,%3}, [%4];" \
        : "=r"((r)[0]), "=r"((r)[1]), "=r"((r)[2]), "=r"((r)[3]) : "r"(addr))

#define MMA_BF16(d, a, b0, b1) \
    asm volatile("mma.sync.aligned.m16n8k16.row.col.f32.bf16.bf16.f32 " \
        "{%0,%1,%2,%3}, {%4,%5,%6,%7}, {%8,%9}, {%0,%1,%2,%3};" \
        : "+f"((d)[0]), "+f"((d)[1]), "+f"((d)[2]), "+f"((d)[3]) \
        : "r"((a)[0]), "r"((a)[1]), "r"((a)[2]), "r"((a)[3]), "r"(b0), "r"(b1))

// ---------------------------------------------------------------------------
// Split fp32 -> (bf16 hi, bf16 lo)
// ---------------------------------------------------------------------------
__global__ __launch_bounds__(256)
void split_bf16_kernel(const float4* __restrict__ src, uint2* __restrict__ hi,
                       uint2* __restrict__ lo, int n4)
{
    int i = blockIdx.x * blockDim.x + threadIdx.x;
    if (i >= n4) return;
    float4 v = src[i];
    __nv_bfloat16 hx = __float2bfloat16(v.x);
    __nv_bfloat16 hy = __float2bfloat16(v.y);
    __nv_bfloat16 hz = __float2bfloat16(v.z);
    __nv_bfloat16 hw = __float2bfloat16(v.w);
    __nv_bfloat16 lx = __float2bfloat16(v.x - __bfloat162float(hx));
    __nv_bfloat16 ly = __float2bfloat16(v.y - __bfloat162float(hy));
    __nv_bfloat16 lz = __float2bfloat16(v.z - __bfloat162float(hz));
    __nv_bfloat16 lw = __float2bfloat16(v.w - __bfloat162float(hw));
    uint2 h, l;
    h.x = (uint32_t)__bfloat16_as_ushort(hx) | ((uint32_t)__bfloat16_as_ushort(hy) << 16);
    h.y = (uint32_t)__bfloat16_as_ushort(hz) | ((uint32_t)__bfloat16_as_ushort(hw) << 16);
    l.x = (uint32_t)__bfloat16_as_ushort(lx) | ((uint32_t)__bfloat16_as_ushort(ly) << 16);
    l.y = (uint32_t)__bfloat16_as_ushort(lz) | ((uint32_t)__bfloat16_as_ushort(lw) << 16);
    hi[i] = h;
    lo[i] = l;
}

// ---------------------------------------------------------------------------
// HMMA GEMM: C[m,n] = sum_k A[m,k]*B[n,k] + bias[n], 3-term bf16 split.
// 128x128 tile, BK=32, 256 threads, warp grid 2(M)x4(N), warp tile 64x32.
// 3-stage cp.async pipeline, padded 80B smem rows (conflict-free ldmatrix).
// K fixed = 1024.
// ---------------------------------------------------------------------------
__global__ __launch_bounds__(256, 1)
void gemm_mma_kernel(const __nv_bfloat16* __restrict__ Ah, const __nv_bfloat16* __restrict__ Al,
                     const __nv_bfloat16* __restrict__ Bh, const __nv_bfloat16* __restrict__ Bl,
                     const float* __restrict__ bias, float* __restrict__ C, int N)
{
    extern __shared__ __align__(128) char smem[];
    const uint32_t sbase = smem_u32(smem);
    const int tid = threadIdx.x;
    const int lane = tid & 31, wid = tid >> 5;
    const int wm = wid >> 2, wn = wid & 3;     // 2 x 4 warp grid
    const int bm = blockIdx.y << 7, bn = blockIdx.x << 7;

    // cp.async fill of one stage (all 4 matrices), 8 x 16B per thread
    auto load_stage = [&](int kc, int st_idx) {
        const uint32_t st = sbase + (uint32_t)st_idx * STG_B;
        const int koff = kc << 5;
#pragma unroll
        for (int i = 0; i < 2; i++) {
            const int idx = tid + (i << 8);          // 0..511
            const int row = idx >> 2;                // 0..127
            const int c = idx & 3;                   // 16B chunk (64B per row)
            const uint32_t so = (uint32_t)(row * ROW_B + c * 16);
            const size_t ga = (size_t)(bm + row) * GK + koff + (c << 3);
            const size_t gb = (size_t)(bn + row) * GK + koff + (c << 3);
            CP_ASYNC16(st + so,             Ah + ga);
            CP_ASYNC16(st + MAT_B + so,     Al + ga);
            CP_ASYNC16(st + 2 * MAT_B + so, Bh + gb);
            CP_ASYNC16(st + 3 * MAT_B + so, Bl + gb);
        }
    };

    // ldmatrix per-lane offsets (within a matrix)
    uint32_t aoff[4], boff[2];
#pragma unroll
    for (int mt = 0; mt < 4; mt++)
        aoff[mt] = (uint32_t)((wm * 64 + mt * 16 + (lane & 15)) * ROW_B + (lane >> 4) * 16);
#pragma unroll
    for (int g = 0; g < 2; g++)
        boff[g] = (uint32_t)((wn * 32 + g * 16 + ((lane >> 4) & 1) * 8 + (lane & 7)) * ROW_B
                             + ((lane >> 3) & 1) * 16);

    float acc[4][4][4];
#pragma unroll
    for (int i = 0; i < 4; i++)
#pragma unroll
        for (int j = 0; j < 4; j++)
#pragma unroll
            for (int r = 0; r < 4; r++) acc[i][j][r] = 0.f;

    load_stage(0, 0); CP_COMMIT();
    load_stage(1, 1); CP_COMMIT();

    int s = 0;
    for (int kc = 0; kc < GKC; kc++) {
        CP_WAIT1();                 // stage for chunk kc is resident
        __syncthreads();            // all warps done with stage being overwritten
        if (kc + 2 < GKC) load_stage(kc + 2, (kc + 2) % 3);
        CP_COMMIT();

        const uint32_t st = sbase + (uint32_t)s * STG_B;
#pragma unroll
        for (int ks = 0; ks < 2; ks++) {
            const uint32_t ko = (uint32_t)(ks * 32);   // 16 k-elems = 32B
            uint32_t ah[4][4], al[4][4], bh[2][4], bl[2][4];
#pragma unroll
            for (int mt = 0; mt < 4; mt++) {
                LDSM_X4(ah[mt], st + aoff[mt] + ko);
                LDSM_X4(al[mt], st + MAT_B + aoff[mt] + ko);
            }
#pragma unroll
            for (int g = 0; g < 2; g++) {
                LDSM_X4(bh[g], st + 2 * MAT_B + boff[g] + ko);
                LDSM_X4(bl[g], st + 3 * MAT_B + boff[g] + ko);
            }
            // product 1: Ah*Bh
#pragma unroll
            for (int mt = 0; mt < 4; mt++)
#pragma unroll
                for (int nt = 0; nt < 4; nt++)
                    MMA_BF16(acc[mt][nt], ah[mt], bh[nt >> 1][(nt & 1) * 2],
                             bh[nt >> 1][(nt & 1) * 2 + 1]);
            // product 2: Ah*Bl
#pragma unroll
            for (int mt = 0; mt < 4; mt++)
#pragma unroll
                for (int nt = 0; nt < 4; nt++)
                    MMA_BF16(acc[mt][nt], ah[mt], bl[nt >> 1][(nt & 1) * 2],
                             bl[nt >> 1][(nt & 1) * 2 + 1]);
            // product 3: Al*Bh
#pragma unroll
            for (int mt = 0; mt < 4; mt++)
#pragma unroll
                for (int nt = 0; nt < 4; nt++)
                    MMA_BF16(acc[mt][nt], al[mt], bh[nt >> 1][(nt & 1) * 2],
                             bh[nt >> 1][(nt & 1) * 2 + 1]);
        }
        s++; if (s == 3) s = 0;
    }

    // Epilogue: c0,c1 -> (row, col..col+1); c2,c3 -> (row+8, ...)
    const int rbase = bm + wm * 64 + (lane >> 2);
    const int cbase = bn + wn * 32 + (lane & 3) * 2;
#pragma unroll
    for (int mt = 0; mt < 4; mt++) {
#pragma unroll
        for (int nt = 0; nt < 4; nt++) {
            const int col = cbase + nt * 8;
            const float b0 = bias[col], b1 = bias[col + 1];
            const int r0 = rbase + mt * 16;
            float2 v0 = make_float2(acc[mt][nt][0] + b0, acc[mt][nt][1] + b1);
            float2 v1 = make_float2(acc[mt][nt][2] + b0, acc[mt][nt][3] + b1);
            *(float2*)(C + (size_t)r0 * N + col) = v0;
            *(float2*)(C + (size_t)(r0 + 8) * N + col) = v1;
        }
    }
}

// ---------------------------------------------------------------------------
// Fused conv(kt=3) -> exact GELU -> LayerNorm(DH) -> mean over L => q_rel
// ---------------------------------------------------------------------------
__global__ __launch_bounds__(512)
void conv_ln_qrel_kernel(const float* __restrict__ conv_w, const float* __restrict__ conv_b,
                         const float* __restrict__ ln_g, const float* __restrict__ ln_b)
{
    const int nh = blockIdx.x;
    const int n = nh >> 4, h = nh & 15;
    const int tid = threadIdx.x;
    const int w = tid >> 5, lane = tid & 31;
    const int d0 = lane, d1 = lane + 32;
    const float* qbase = g_qkv + (size_t)n * L_SEQ * QKV_STRIDE + h * DH;

    const float cw00 = conv_w[d0 * 3 + 0], cw01 = conv_w[d0 * 3 + 1], cw02 = conv_w[d0 * 3 + 2];
    const float cw10 = conv_w[d1 * 3 + 0], cw11 = conv_w[d1 * 3 + 1], cw12 = conv_w[d1 * 3 + 2];
    const float cb0 = conv_b[d0], cb1 = conv_b[d1];
    const float lg0 = ln_g[d0], lb0 = ln_b[d0];
    const float lg1 = ln_g[d1], lb1 = ln_b[d1];

    float p0 = 0.f, p1 = 0.f;
    for (int t = w; t < L_SEQ; t += 16) {
        float c0 = cb0, c1 = cb1;
        {
            const float* r = qbase + (size_t)t * QKV_STRIDE;
            c0 = fmaf(r[d0], cw02, c0); c1 = fmaf(r[d1], cw12, c1);
        }
        if (t >= 1) {
            const float* r = qbase + (size_t)(t - 1) * QKV_STRIDE;
            c0 = fmaf(r[d0], cw01, c0); c1 = fmaf(r[d1], cw11, c1);
        }
        if (t >= 2) {
            const float* r = qbase + (size_t)(t - 2) * QKV_STRIDE;
            c0 = fmaf(r[d0], cw00, c0); c1 = fmaf(r[d1], cw10, c1);
        }
        float g0 = 0.5f * c0 * (1.f + erff(c0 * 0.70710678118654752f));
        float g1 = 0.5f * c1 * (1.f + erff(c1 * 0.70710678118654752f));
        float sv = g0 + g1, sq = g0 * g0 + g1 * g1;
#pragma unroll
        for (int o = 16; o; o >>= 1) {
            sv += __shfl_xor_sync(0xffffffffu, sv, o);
            sq += __shfl_xor_sync(0xffffffffu, sq, o);
        }
        float mu = sv * (1.f / 64.f);
        float var = sq * (1.f / 64.f) - mu * mu;
        float rs = rsqrtf(var + 1e-5f);
        p0 += (g0 - mu) * rs * lg0 + lb0;
        p1 += (g1 - mu) * rs * lg1 + lb1;
    }

    __shared__ float part[16][64];
    part[w][d0] = p0;
    part[w][d1] = p1;
    __syncthreads();
    if (tid < 64) {
        float sv = 0.f;
#pragma unroll
        for (int i = 0; i < 16; i++) sv += part[i][tid];
        g_qs[nh * 64 + tid] = sv * (0.125f / 2048.f);
    }
}

// ---------------------------------------------------------------------------
__global__ __launch_bounds__(256)
void wk_kernel()
{
    const int nh = blockIdx.x;
    const int n = nh >> 4, h = nh & 15;
    const int tid = threadIdx.x;
    __shared__ float4 qs4[16];
    if (tid < 16) qs4[tid] = ((const float4*)(g_qs + nh * 64))[tid];
    __syncthreads();

    const float* kbase = g_qkv + (size_t)n * L_SEQ * QKV_STRIDE + D_MODEL + h * DH;
    float wk[8];
    float la = 0.f;
#pragma unroll
    for (int i = 0; i < 8; i++) {
        int l = tid + i * 256;
        const float4* kr = (const float4*)(kbase + (size_t)l * QKV_STRIDE);
        float a = 0.f;
#pragma unroll
        for (int d4 = 0; d4 < 16; d4++) {
            float4 kv = kr[d4]; float4 q = qs4[d4];
            a = fmaf(q.x, kv.x, a); a = fmaf(q.y, kv.y, a);
            a = fmaf(q.z, kv.z, a); a = fmaf(q.w, kv.w, a);
        }
        wk[i] = a;
        la += fabsf(a);
    }
    __shared__ float red[256];
    red[tid] = la;
    __syncthreads();
    for (int o = 128; o; o >>= 1) {
        if (tid < o) red[tid] += red[tid + o];
        __syncthreads();
    }
    const float scale = 1.f / (red[0] + 1e-6f);
#pragma unroll
    for (int i = 0; i < 8; i++)
        g_wn[nh * L_SEQ + tid + i * 256] = wk[i] * scale;
}

// ---------------------------------------------------------------------------
__global__ __launch_bounds__(256)
void attn_kernel()
{
    const int t_tile = blockIdx.x;
    const int nh = blockIdx.y;
    const int n = nh >> 4, h = nh & 15;
    const int tid = threadIdx.x;
    const int tx = tid & 15, ty = tid >> 4;
    const int t0 = t_tile * 64;

    __shared__ float w_sh[128];
    __shared__ float Vs[64][64];

    float acc[4][4];
#pragma unroll
    for (int i = 0; i < 4; i++)
#pragma unroll
        for (int j = 0; j < 4; j++) acc[i][j] = 0.f;

    const float* vbase = g_qkv + (size_t)n * L_SEQ * QKV_STRIDE + 2 * D_MODEL + h * DH;
    const float* wn = g_wn + nh * L_SEQ;

    for (int s0 = 0; s0 <= t0; s0 += 64) {
        if (tid < 128) {
            int lag = t0 - s0 - 63 + tid;
            w_sh[tid] = (lag >= 0) ? wn[lag] : 0.f;
        }
#pragma unroll
        for (int it = 0; it < 4; it++) {
            int row = (tid >> 4) + it * 16;
            int col = (tid & 15) * 4;
            float4 v = *(const float4*)(vbase + (size_t)(s0 + row) * QKV_STRIDE + col);
            *(float4*)&Vs[row][col] = v;
        }
        __syncthreads();
#pragma unroll 8
        for (int sI = 0; sI < 64; sI++) {
            float4 v4 = *(const float4*)&Vs[sI][tx * 4];
            int base = ty * 4 + 63 - sI;
#pragma unroll
            for (int i = 0; i < 4; i++) {
                float wv = w_sh[base + i];
                acc[i][0] = fmaf(wv, v4.x, acc[i][0]);
                acc[i][1] = fmaf(wv, v4.y, acc[i][1]);
                acc[i][2] = fmaf(wv, v4.z, acc[i][2]);
                acc[i][3] = fmaf(wv, v4.w, acc[i][3]);
            }
        }
        __syncthreads();
    }

    float* mbase = g_merged + (size_t)n * L_SEQ * D_MODEL + h * DH;
#pragma unroll
    for (int i = 0; i < 4; i++) {
        int t = t0 + ty * 4 + i;
        float4 o = make_float4(acc[i][0], acc[i][1], acc[i][2], acc[i][3]);
        *(float4*)(mbase + (size_t)t * D_MODEL + tx * 4) = o;
    }
}

__global__ void fill_kernel(float* p, int nfill, float v)
{
    int i = blockIdx.x * blockDim.x + threadIdx.x;
    if (i < nfill) p[i] = v;
}

// ---------------------------------------------------------------------------
extern "C" void kernel_launch(void* const* d_in, const int* in_sizes, int n_in,
                              void* d_out, int out_size)
{
    const float* x      = (const float*)d_in[0];
    const float* in_w   = (const float*)d_in[1];
    const float* in_b   = (const float*)d_in[2];
    const float* conv_w = (const float*)d_in[3];
    const float* conv_b = (const float*)d_in[4];
    const float* ln_g   = (const float*)d_in[5];
    const float* ln_b   = (const float*)d_in[6];
    const float* out_w  = (const float*)d_in[7];
    const float* out_b  = (const float*)d_in[8];
    float* out = (float*)d_out;

    void* p;
    cudaGetSymbolAddress(&p, g_qkv);    float* qkv = (float*)p;
    cudaGetSymbolAddress(&p, g_merged); float* merged = (float*)p;
    cudaGetSymbolAddress(&p, g_ah);     __nv_bfloat16* ah = (__nv_bfloat16*)p;
    cudaGetSymbolAddress(&p, g_al);     __nv_bfloat16* al = (__nv_bfloat16*)p;
    cudaGetSymbolAddress(&p, g_bh);     __nv_bfloat16* bh = (__nv_bfloat16*)p;
    cudaGetSymbolAddress(&p, g_bl);     __nv_bfloat16* bl = (__nv_bfloat16*)p;

    cudaFuncSetAttribute(gemm_mma_kernel, cudaFuncAttributeMaxDynamicSharedMemorySize, GT_SMEM);

    // GEMM1: qkv = x @ in_proj_w^T + in_proj_b  (4096 x 3072, K=1024)
    split_bf16_kernel<<<4096, 256>>>((const float4*)x, (uint2*)ah, (uint2*)al, 4096 * 1024 / 4);
    split_bf16_kernel<<<3072, 256>>>((const float4*)in_w, (uint2*)bh, (uint2*)bl, 3072 * 1024 / 4);
    gemm_mma_kernel<<<dim3(3072 / 128, 4096 / 128), 256, GT_SMEM>>>(ah, al, bh, bl, in_b, qkv, 3 * D_MODEL);

    // conv -> gelu -> LN -> mean => q_rel ; Wk -> Wn ; Toeplitz attention
    conv_ln_qrel_kernel<<<NH_TOT, 512>>>(conv_w, conv_b, ln_g, ln_b);
    wk_kernel<<<NH_TOT, 256>>>();
    attn_kernel<<<dim3(L_SEQ / 64, NH_TOT), 256>>>();

    // GEMM2: out = merged @ out_w^T + out_b  (4096 x 1024, K=1024)
    split_bf16_kernel<<<4096, 256>>>((const float4*)merged, (uint2*)ah, (uint2*)al, 4096 * 1024 / 4);
    split_bf16_kernel<<<1024, 256>>>((const float4*)out_w, (uint2*)bh, (uint2*)bl, 1024 * 1024 / 4);
    gemm_mma_kernel<<<dim3(1024 / 128, 4096 / 128), 256, GT_SMEM>>>(ah, al, bh, bl, out_b, out, D_MODEL);

    // mock attention weights
    int nmock = out_size - OUT_ELEMS;
    if (nmock > 0)
        fill_kernel<<<(nmock + 255) / 256, 256>>>(out + OUT_ELEMS, nmock, 1.0f / (float)L_SEQ);
}

// round 4
// speedup vs baseline: 2.3724x; 1.4385x over previous
#include <cuda_runtime.h>
#include <cuda_bf16.h>
#include <math.h>
#include <stdint.h>

// Problem constants
#define NBATCH 2
#define L_SEQ 2048
#define D_MODEL 1024
#define H_HEADS 16
#define DH 64
#define QKV_STRIDE 3072
#define NH_TOT (NBATCH * H_HEADS)
#define OUT_ELEMS (NBATCH * L_SEQ * D_MODEL)
#define GK 1024
#define GKC 32
// gemm smem: 3 stages x 4 matrices x 128 rows x 80B
#define ROW_B 80
#define MAT_B (128 * ROW_B)
#define STG_B (4 * MAT_B)
#define GT_SMEM (3 * STG_B)

// Static device scratch
__device__ float g_qkv[(size_t)NBATCH * L_SEQ * QKV_STRIDE];
__device__ float g_qs[NH_TOT * DH];
__device__ float g_cpart[NH_TOT * 16 * DH];
__device__ __align__(16) __nv_bfloat16 g_ah[(size_t)4096 * 1024];   // gemm1 A split / merged split
__device__ __align__(16) __nv_bfloat16 g_al[(size_t)4096 * 1024];
__device__ __align__(16) __nv_bfloat16 g_bh[(size_t)3072 * 1024];   // weight splits
__device__ __align__(16) __nv_bfloat16 g_bl[(size_t)3072 * 1024];
__device__ __align__(16) __nv_bfloat16 g_vh[(size_t)4096 * 1024];   // V split
__device__ __align__(16) __nv_bfloat16 g_vl[(size_t)4096 * 1024];
__device__ __align__(16) __nv_bfloat16 g_wnh[NH_TOT * L_SEQ];       // Wn split
__device__ __align__(16) __nv_bfloat16 g_wnl[NH_TOT * L_SEQ];

// ---------------------------------------------------------------------------
__device__ __forceinline__ uint32_t smem_u32(const void* p) {
    uint32_t a;
    asm("{ .reg .u64 t; cvta.to.shared.u64 t, %1; cvt.u32.u64 %0, t; }" : "=r"(a) : "l"(p));
    return a;
}

#define CP_ASYNC16(dst, src) \
    asm volatile("cp.async.cg.shared.global [%0], [%1], 16;" :: "r"(dst), "l"(src))
#define CP_COMMIT() asm volatile("cp.async.commit_group;" ::: "memory")
#define CP_WAIT1()  asm volatile("cp.async.wait_group 1;" ::: "memory")
#define CP_WAIT0()  asm volatile("cp.async.wait_group 0;" ::: "memory")

#define LDSM_X4(r, addr) \
    asm volatile("ldmatrix.sync.aligned.m8n8.x4.shared.b16 {%0,%1,%2,%3}, [%4];" \
        : "=r"((r)[0]), "=r"((r)[1]), "=r"((r)[2]), "=r"((r)[3]) : "r"(addr))

#define LDSM_X4_T(r, addr) \
    asm volatile("ldmatrix.sync.aligned.m8n8.x4.trans.shared.b16 {%0,%1,%2,%3}, [%4];" \
        : "=r"((r)[0]), "=r"((r)[1]), "=r"((r)[2]), "=r"((r)[3]) : "r"(addr))

#define MMA_BF16(d, a, b0, b1) \
    asm volatile("mma.sync.aligned.m16n8k16.row.col.f32.bf16.bf16.f32 " \
        "{%0,%1,%2,%3}, {%4,%5,%6,%7}, {%8,%9}, {%0,%1,%2,%3};" \
        : "+f"((d)[0]), "+f"((d)[1]), "+f"((d)[2]), "+f"((d)[3]) \
        : "r"((a)[0]), "r"((a)[1]), "r"((a)[2]), "r"((a)[3]), "r"(b0), "r"(b1))

__device__ __forceinline__ uint32_t bfpack(float a, float b) {
    __nv_bfloat16 ha = __float2bfloat16(a), hb = __float2bfloat16(b);
    return (uint32_t)__bfloat16_as_ushort(ha) | ((uint32_t)__bfloat16_as_ushort(hb) << 16);
}

// ---------------------------------------------------------------------------
// Split fp32 -> (bf16 hi, bf16 lo)
// ---------------------------------------------------------------------------
__global__ __launch_bounds__(256)
void split_bf16_kernel(const float4* __restrict__ src, uint2* __restrict__ hi,
                       uint2* __restrict__ lo, int n4)
{
    int i = blockIdx.x * blockDim.x + threadIdx.x;
    if (i >= n4) return;
    float4 v = src[i];
    __nv_bfloat16 hx = __float2bfloat16(v.x), hy = __float2bfloat16(v.y);
    __nv_bfloat16 hz = __float2bfloat16(v.z), hw = __float2bfloat16(v.w);
    uint2 h, l;
    h.x = (uint32_t)__bfloat16_as_ushort(hx) | ((uint32_t)__bfloat16_as_ushort(hy) << 16);
    h.y = (uint32_t)__bfloat16_as_ushort(hz) | ((uint32_t)__bfloat16_as_ushort(hw) << 16);
    l.x = bfpack(v.x - __bfloat162float(hx), v.y - __bfloat162float(hy));
    l.y = bfpack(v.z - __bfloat162float(hz), v.w - __bfloat162float(hw));
    hi[i] = h;
    lo[i] = l;
}

// Split the V slice of qkv (cols 2048..3071) into g_vh/g_vl [4096][1024]
__global__ __launch_bounds__(256)
void split_v_kernel()
{
    int i = blockIdx.x * 256 + threadIdx.x;
    int r = i >> 8, c4 = (i & 255) << 2;
    float4 v = *(const float4*)(g_qkv + (size_t)r * QKV_STRIDE + 2048 + c4);
    __nv_bfloat16 hx = __float2bfloat16(v.x), hy = __float2bfloat16(v.y);
    __nv_bfloat16 hz = __float2bfloat16(v.z), hw = __float2bfloat16(v.w);
    uint2 h, l;
    h.x = (uint32_t)__bfloat16_as_ushort(hx) | ((uint32_t)__bfloat16_as_ushort(hy) << 16);
    h.y = (uint32_t)__bfloat16_as_ushort(hz) | ((uint32_t)__bfloat16_as_ushort(hw) << 16);
    l.x = bfpack(v.x - __bfloat162float(hx), v.y - __bfloat162float(hy));
    l.y = bfpack(v.z - __bfloat162float(hz), v.w - __bfloat162float(hw));
    ((uint2*)g_vh)[(size_t)r * 256 + (c4 >> 2)] = h;
    ((uint2*)g_vl)[(size_t)r * 256 + (c4 >> 2)] = l;
}

// ---------------------------------------------------------------------------
// HMMA GEMM (proven in round 3)
// ---------------------------------------------------------------------------
__global__ __launch_bounds__(256, 1)
void gemm_mma_kernel(const __nv_bfloat16* __restrict__ Ah, const __nv_bfloat16* __restrict__ Al,
                     const __nv_bfloat16* __restrict__ Bh, const __nv_bfloat16* __restrict__ Bl,
                     const float* __restrict__ bias, float* __restrict__ C, int N)
{
    extern __shared__ __align__(128) char smem[];
    const uint32_t sbase = smem_u32(smem);
    const int tid = threadIdx.x;
    const int lane = tid & 31, wid = tid >> 5;
    const int wm = wid >> 2, wn = wid & 3;
    const int bm = blockIdx.y << 7, bn = blockIdx.x << 7;

    auto load_stage = [&](int kc, int st_idx) {
        const uint32_t st = sbase + (uint32_t)st_idx * STG_B;
        const int koff = kc << 5;
#pragma unroll
        for (int i = 0; i < 2; i++) {
            const int idx = tid + (i << 8);
            const int row = idx >> 2;
            const int c = idx & 3;
            const uint32_t so = (uint32_t)(row * ROW_B + c * 16);
            const size_t ga = (size_t)(bm + row) * GK + koff + (c << 3);
            const size_t gb = (size_t)(bn + row) * GK + koff + (c << 3);
            CP_ASYNC16(st + so,             Ah + ga);
            CP_ASYNC16(st + MAT_B + so,     Al + ga);
            CP_ASYNC16(st + 2 * MAT_B + so, Bh + gb);
            CP_ASYNC16(st + 3 * MAT_B + so, Bl + gb);
        }
    };

    uint32_t aoff[4], boff[2];
#pragma unroll
    for (int mt = 0; mt < 4; mt++)
        aoff[mt] = (uint32_t)((wm * 64 + mt * 16 + (lane & 15)) * ROW_B + (lane >> 4) * 16);
#pragma unroll
    for (int g = 0; g < 2; g++)
        boff[g] = (uint32_t)((wn * 32 + g * 16 + ((lane >> 4) & 1) * 8 + (lane & 7)) * ROW_B
                             + ((lane >> 3) & 1) * 16);

    float acc[4][4][4];
#pragma unroll
    for (int i = 0; i < 4; i++)
#pragma unroll
        for (int j = 0; j < 4; j++)
#pragma unroll
            for (int r = 0; r < 4; r++) acc[i][j][r] = 0.f;

    load_stage(0, 0); CP_COMMIT();
    load_stage(1, 1); CP_COMMIT();

    int s = 0;
    for (int kc = 0; kc < GKC; kc++) {
        CP_WAIT1();
        __syncthreads();
        if (kc + 2 < GKC) load_stage(kc + 2, (kc + 2) % 3);
        CP_COMMIT();

        const uint32_t st = sbase + (uint32_t)s * STG_B;
#pragma unroll
        for (int ks = 0; ks < 2; ks++) {
            const uint32_t ko = (uint32_t)(ks * 32);
            uint32_t ah[4][4], al[4][4], bh[2][4], bl[2][4];
#pragma unroll
            for (int mt = 0; mt < 4; mt++) {
                LDSM_X4(ah[mt], st + aoff[mt] + ko);
                LDSM_X4(al[mt], st + MAT_B + aoff[mt] + ko);
            }
#pragma unroll
            for (int g = 0; g < 2; g++) {
                LDSM_X4(bh[g], st + 2 * MAT_B + boff[g] + ko);
                LDSM_X4(bl[g], st + 3 * MAT_B + boff[g] + ko);
            }
#pragma unroll
            for (int mt = 0; mt < 4; mt++)
#pragma unroll
                for (int nt = 0; nt < 4; nt++)
                    MMA_BF16(acc[mt][nt], ah[mt], bh[nt >> 1][(nt & 1) * 2],
                             bh[nt >> 1][(nt & 1) * 2 + 1]);
#pragma unroll
            for (int mt = 0; mt < 4; mt++)
#pragma unroll
                for (int nt = 0; nt < 4; nt++)
                    MMA_BF16(acc[mt][nt], ah[mt], bl[nt >> 1][(nt & 1) * 2],
                             bl[nt >> 1][(nt & 1) * 2 + 1]);
#pragma unroll
            for (int mt = 0; mt < 4; mt++)
#pragma unroll
                for (int nt = 0; nt < 4; nt++)
                    MMA_BF16(acc[mt][nt], al[mt], bh[nt >> 1][(nt & 1) * 2],
                             bh[nt >> 1][(nt & 1) * 2 + 1]);
        }
        s++; if (s == 3) s = 0;
    }

    const int rbase = bm + wm * 64 + (lane >> 2);
    const int cbase = bn + wn * 32 + (lane & 3) * 2;
#pragma unroll
    for (int mt = 0; mt < 4; mt++) {
#pragma unroll
        for (int nt = 0; nt < 4; nt++) {
            const int col = cbase + nt * 8;
            const float b0 = bias[col], b1 = bias[col + 1];
            const int r0 = rbase + mt * 16;
            float2 v0 = make_float2(acc[mt][nt][0] + b0, acc[mt][nt][1] + b1);
            float2 v1 = make_float2(acc[mt][nt][2] + b0, acc[mt][nt][3] + b1);
            *(float2*)(C + (size_t)r0 * N + col) = v0;
            *(float2*)(C + (size_t)(r0 + 8) * N + col) = v1;
        }
    }
}

// ---------------------------------------------------------------------------
// conv -> GELU -> LN -> partial mean over a 128-t chunk. Grid (16, 32).
// ---------------------------------------------------------------------------
__global__ __launch_bounds__(256)
void conv_part_kernel(const float* __restrict__ conv_w, const float* __restrict__ conv_b,
                      const float* __restrict__ ln_g, const float* __restrict__ ln_b)
{
    const int chunk = blockIdx.x;
    const int nh = blockIdx.y;
    const int n = nh >> 4, h = nh & 15;
    const int tid = threadIdx.x;
    const int w = tid >> 5, lane = tid & 31;
    const int d0 = lane, d1 = lane + 32;
    const float* qbase = g_qkv + (size_t)n * L_SEQ * QKV_STRIDE + h * DH;

    const float cw00 = conv_w[d0 * 3 + 0], cw01 = conv_w[d0 * 3 + 1], cw02 = conv_w[d0 * 3 + 2];
    const float cw10 = conv_w[d1 * 3 + 0], cw11 = conv_w[d1 * 3 + 1], cw12 = conv_w[d1 * 3 + 2];
    const float cb0 = conv_b[d0], cb1 = conv_b[d1];
    const float lg0 = ln_g[d0], lb0 = ln_b[d0];
    const float lg1 = ln_g[d1], lb1 = ln_b[d1];

    float p0 = 0.f, p1 = 0.f;
#pragma unroll 4
    for (int i = 0; i < 16; i++) {
        const int t = chunk * 128 + (w << 4) + i;
        float c0 = cb0, c1 = cb1;
        {
            const float* r = qbase + (size_t)t * QKV_STRIDE;
            c0 = fmaf(r[d0], cw02, c0); c1 = fmaf(r[d1], cw12, c1);
        }
        if (t >= 1) {
            const float* r = qbase + (size_t)(t - 1) * QKV_STRIDE;
            c0 = fmaf(r[d0], cw01, c0); c1 = fmaf(r[d1], cw11, c1);
        }
        if (t >= 2) {
            const float* r = qbase + (size_t)(t - 2) * QKV_STRIDE;
            c0 = fmaf(r[d0], cw00, c0); c1 = fmaf(r[d1], cw10, c1);
        }
        float g0 = 0.5f * c0 * (1.f + erff(c0 * 0.70710678118654752f));
        float g1 = 0.5f * c1 * (1.f + erff(c1 * 0.70710678118654752f));
        float sv = g0 + g1, sq = g0 * g0 + g1 * g1;
#pragma unroll
        for (int o = 16; o; o >>= 1) {
            sv += __shfl_xor_sync(0xffffffffu, sv, o);
            sq += __shfl_xor_sync(0xffffffffu, sq, o);
        }
        float mu = sv * (1.f / 64.f);
        float var = sq * (1.f / 64.f) - mu * mu;
        float rs = rsqrtf(var + 1e-5f);
        p0 += (g0 - mu) * rs * lg0 + lb0;
        p1 += (g1 - mu) * rs * lg1 + lb1;
    }

    __shared__ float part[8][64];
    part[w][d0] = p0;
    part[w][d1] = p1;
    __syncthreads();
    if (tid < 64) {
        float sv = 0.f;
#pragma unroll
        for (int i = 0; i < 8; i++) sv += part[i][tid];
        g_cpart[(nh * 16 + chunk) * 64 + tid] = sv;
    }
}

__global__ __launch_bounds__(64)
void conv_reduce_kernel()
{
    const int nh = blockIdx.x;
    const int tid = threadIdx.x;
    float sv = 0.f;
#pragma unroll
    for (int i = 0; i < 16; i++) sv += g_cpart[(nh * 16 + i) * 64 + tid];
    g_qs[nh * 64 + tid] = sv * (0.125f / 2048.f);
}

// ---------------------------------------------------------------------------
// Wk + L1 normalization -> Wn (bf16 hi/lo split)
// ---------------------------------------------------------------------------
__global__ __launch_bounds__(256)
void wk_kernel()
{
    const int nh = blockIdx.x;
    const int n = nh >> 4, h = nh & 15;
    const int tid = threadIdx.x;
    __shared__ float4 qs4[16];
    if (tid < 16) qs4[tid] = ((const float4*)(g_qs + nh * 64))[tid];
    __syncthreads();

    const float* kbase = g_qkv + (size_t)n * L_SEQ * QKV_STRIDE + D_MODEL + h * DH;
    float wk[8];
    float la = 0.f;
#pragma unroll
    for (int i = 0; i < 8; i++) {
        int l = tid + i * 256;
        const float4* kr = (const float4*)(kbase + (size_t)l * QKV_STRIDE);
        float a = 0.f;
#pragma unroll
        for (int d4 = 0; d4 < 16; d4++) {
            float4 kv = kr[d4]; float4 q = qs4[d4];
            a = fmaf(q.x, kv.x, a); a = fmaf(q.y, kv.y, a);
            a = fmaf(q.z, kv.z, a); a = fmaf(q.w, kv.w, a);
        }
        wk[i] = a;
        la += fabsf(a);
    }
    __shared__ float red[256];
    red[tid] = la;
    __syncthreads();
    for (int o = 128; o; o >>= 1) {
        if (tid < o) red[tid] += red[tid + o];
        __syncthreads();
    }
    const float scale = 1.f / (red[0] + 1e-6f);
#pragma unroll
    for (int i = 0; i < 8; i++) {
        const float wv = wk[i] * scale;
        __nv_bfloat16 hh = __float2bfloat16(wv);
        g_wnh[nh * L_SEQ + tid + i * 256] = hh;
        g_wnl[nh * L_SEQ + tid + i * 256] = __float2bfloat16(wv - __bfloat162float(hh));
    }
}

// ---------------------------------------------------------------------------
// Toeplitz attention via HMMA. Block = 64 t x 64 d, 4 warps (m16 each).
// T tile built in registers from 127-entry Wn smem segment; V via cp.async +
// ldmatrix.x4.trans (144B padded rows). 3-term bf16 split. Epilogue writes the
// bf16 hi/lo split of merged directly into g_ah/g_al for GEMM2.
// ---------------------------------------------------------------------------
#define VROW 144
__global__ __launch_bounds__(128, 1)
void attn_mma_kernel()
{
    const int t_tile = blockIdx.x;
    const int nh = blockIdx.y;
    const int n = nh >> 4, h = nh & 15;
    const int tid = threadIdx.x;
    const int lane = tid & 31, wid = tid >> 5;
    const int t0 = t_tile << 6;
    const int nc = t_tile + 1;

    __shared__ __align__(16) char vsm[2][2][64 * VROW];
    __shared__ __nv_bfloat16 wsh[2][128], wsl[2][128];

    const uint32_t vbase = smem_u32(vsm);
    const __nv_bfloat16* wnh = g_wnh + nh * L_SEQ;
    const __nv_bfloat16* wnl = g_wnl + nh * L_SEQ;
    const __nv_bfloat16 zero = __float2bfloat16(0.f);

    auto load_w = [&](int c, int buf) {
        if (tid < 127) {
            const int lag = t0 - (c << 6) - 63 + tid;
            wsh[buf][tid] = (lag >= 0) ? wnh[lag] : zero;
            wsl[buf][tid] = (lag >= 0) ? wnl[lag] : zero;
        }
    };
    auto load_v = [&](int c, int buf) {
#pragma unroll
        for (int i = 0; i < 4; i++) {
            const int idx = tid + (i << 7);
            const int row = idx >> 3, ch = idx & 7;
            const size_t g = (size_t)(n * L_SEQ + (c << 6) + row) * 1024 + h * DH + (ch << 3);
            const uint32_t soh = (uint32_t)(buf * (2 * 64 * VROW) + row * VROW + (ch << 4));
            CP_ASYNC16(vbase + soh,             g_vh + g);
            CP_ASYNC16(vbase + soh + 64 * VROW, g_vl + g);
        }
    };

    float acc[8][4];
#pragma unroll
    for (int i = 0; i < 8; i++)
#pragma unroll
        for (int j = 0; j < 4; j++) acc[i][j] = 0.f;

    load_w(0, 0); load_v(0, 0); CP_COMMIT();

    const int r0 = lane >> 2;
    const int c0 = (lane & 3) << 1;
    const uint32_t lrow = (uint32_t)(lane & 15);
    const uint32_t lcol = (uint32_t)((lane >> 4) << 4);

    for (int c = 0; c < nc; c++) {
        const int buf = c & 1;
        if (c + 1 < nc) {
            load_w(c + 1, buf ^ 1);
            load_v(c + 1, buf ^ 1);
            CP_COMMIT();
            CP_WAIT1();
        } else {
            CP_WAIT0();
        }
        __syncthreads();

        const __nv_bfloat16* wh = wsh[buf];
        const __nv_bfloat16* wl = wsl[buf];
        const uint32_t vh_s = vbase + (uint32_t)buf * (2 * 64 * VROW);
        const uint32_t vl_s = vh_s + 64 * VROW;

#pragma unroll
        for (int ks = 0; ks < 4; ks++) {
            const int jb = 63 + (wid << 4) + r0 - (ks << 4) - c0;
            uint32_t ah4[4], al4[4];
            {
                uint32_t p0 = (uint32_t)__bfloat16_as_ushort(wh[jb]) |
                              ((uint32_t)__bfloat16_as_ushort(wh[jb - 1]) << 16);
                uint32_t p1 = (uint32_t)__bfloat16_as_ushort(wh[jb + 8]) |
                              ((uint32_t)__bfloat16_as_ushort(wh[jb + 7]) << 16);
                uint32_t p2 = (uint32_t)__bfloat16_as_ushort(wh[jb - 8]) |
                              ((uint32_t)__bfloat16_as_ushort(wh[jb - 9]) << 16);
                ah4[0] = p0; ah4[1] = p1; ah4[2] = p2; ah4[3] = p0;
                uint32_t q0 = (uint32_t)__bfloat16_as_ushort(wl[jb]) |
                              ((uint32_t)__bfloat16_as_ushort(wl[jb - 1]) << 16);
                uint32_t q1 = (uint32_t)__bfloat16_as_ushort(wl[jb + 8]) |
                              ((uint32_t)__bfloat16_as_ushort(wl[jb + 7]) << 16);
                uint32_t q2 = (uint32_t)__bfloat16_as_ushort(wl[jb - 8]) |
                              ((uint32_t)__bfloat16_as_ushort(wl[jb - 9]) << 16);
                al4[0] = q0; al4[1] = q1; al4[2] = q2; al4[3] = q0;
            }
            const uint32_t radd = (uint32_t)((ks * 16 + lrow) * VROW) + lcol;
#pragma unroll
            for (int g = 0; g < 4; g++) {
                uint32_t bh4[4], bl4[4];
                const uint32_t ga = radd + (uint32_t)(g << 5);
                LDSM_X4_T(bh4, vh_s + ga);
                LDSM_X4_T(bl4, vl_s + ga);
                MMA_BF16(acc[g * 2],     ah4, bh4[0], bh4[1]);
                MMA_BF16(acc[g * 2 + 1], ah4, bh4[2], bh4[3]);
                MMA_BF16(acc[g * 2],     ah4, bl4[0], bl4[1]);
                MMA_BF16(acc[g * 2 + 1], ah4, bl4[2], bl4[3]);
                MMA_BF16(acc[g * 2],     al4, bh4[0], bh4[1]);
                MMA_BF16(acc[g * 2 + 1], al4, bh4[2], bh4[3]);
            }
        }
        __syncthreads();
    }

    const size_t rA = (size_t)(n * L_SEQ + t0 + (wid << 4) + r0);
    uint32_t* mh32 = (uint32_t*)g_ah;
    uint32_t* ml32 = (uint32_t*)g_al;
#pragma unroll
    for (int nb = 0; nb < 8; nb++) {
        const int col = h * DH + nb * 8 + c0;
        {
            float v0 = acc[nb][0], v1 = acc[nb][1];
            __nv_bfloat16 h0 = __float2bfloat16(v0), h1 = __float2bfloat16(v1);
            uint32_t ph = (uint32_t)__bfloat16_as_ushort(h0) |
                          ((uint32_t)__bfloat16_as_ushort(h1) << 16);
            uint32_t pl = bfpack(v0 - __bfloat162float(h0), v1 - __bfloat162float(h1));
            mh32[(rA * 1024 + col) >> 1] = ph;
            ml32[(rA * 1024 + col) >> 1] = pl;
        }
        {
            float v0 = acc[nb][2], v1 = acc[nb][3];
            __nv_bfloat16 h0 = __float2bfloat16(v0), h1 = __float2bfloat16(v1);
            uint32_t ph = (uint32_t)__bfloat16_as_ushort(h0) |
                          ((uint32_t)__bfloat16_as_ushort(h1) << 16);
            uint32_t pl = bfpack(v0 - __bfloat162float(h0), v1 - __bfloat162float(h1));
            mh32[((rA + 8) * 1024 + col) >> 1] = ph;
            ml32[((rA + 8) * 1024 + col) >> 1] = pl;
        }
    }
}

__global__ void fill_kernel(float* p, int nfill, float v)
{
    int i = blockIdx.x * blockDim.x + threadIdx.x;
    if (i < nfill) p[i] = v;
}

// ---------------------------------------------------------------------------
extern "C" void kernel_launch(void* const* d_in, const int* in_sizes, int n_in,
                              void* d_out, int out_size)
{
    const float* x      = (const float*)d_in[0];
    const float* in_w   = (const float*)d_in[1];
    const float* in_b   = (const float*)d_in[2];
    const float* conv_w = (const float*)d_in[3];
    const float* conv_b = (const float*)d_in[4];
    const float* ln_g   = (const float*)d_in[5];
    const float* ln_b   = (const float*)d_in[6];
    const float* out_w  = (const float*)d_in[7];
    const float* out_b  = (const float*)d_in[8];
    float* out = (float*)d_out;

    void* p;
    cudaGetSymbolAddress(&p, g_qkv);    float* qkv = (float*)p;
    cudaGetSymbolAddress(&p, g_ah);     __nv_bfloat16* ah = (__nv_bfloat16*)p;
    cudaGetSymbolAddress(&p, g_al);     __nv_bfloat16* al = (__nv_bfloat16*)p;
    cudaGetSymbolAddress(&p, g_bh);     __nv_bfloat16* bh = (__nv_bfloat16*)p;
    cudaGetSymbolAddress(&p, g_bl);     __nv_bfloat16* bl = (__nv_bfloat16*)p;

    cudaFuncSetAttribute(gemm_mma_kernel, cudaFuncAttributeMaxDynamicSharedMemorySize, GT_SMEM);

    // GEMM1: qkv = x @ in_proj_w^T + in_proj_b
    split_bf16_kernel<<<4096, 256>>>((const float4*)x, (uint2*)ah, (uint2*)al, 4096 * 1024 / 4);
    split_bf16_kernel<<<3072, 256>>>((const float4*)in_w, (uint2*)bh, (uint2*)bl, 3072 * 1024 / 4);
    gemm_mma_kernel<<<dim3(3072 / 128, 4096 / 128), 256, GT_SMEM>>>(ah, al, bh, bl, in_b, qkv, 3 * D_MODEL);

    // V split for tensor-core attention
    split_v_kernel<<<4096, 256>>>();

    // conv -> gelu -> LN -> mean => q_rel
    conv_part_kernel<<<dim3(16, NH_TOT), 256>>>(conv_w, conv_b, ln_g, ln_b);
    conv_reduce_kernel<<<NH_TOT, 64>>>();

    // Wk -> Wn (bf16 split)
    wk_kernel<<<NH_TOT, 256>>>();

    // causal Toeplitz attention (HMMA) -> writes merged split into g_ah/g_al
    attn_mma_kernel<<<dim3(L_SEQ / 64, NH_TOT), 128>>>();

    // GEMM2: out = merged @ out_w^T + out_b
    split_bf16_kernel<<<1024, 256>>>((const float4*)out_w, (uint2*)bh, (uint2*)bl, 1024 * 1024 / 4);
    gemm_mma_kernel<<<dim3(1024 / 128, 4096 / 128), 256, GT_SMEM>>>(ah, al, bh, bl, out_b, out, D_MODEL);

    // mock attention weights
    int nmock = out_size - OUT_ELEMS;
    if (nmock > 0)
        fill_kernel<<<(nmock + 255) / 256, 256>>>(out + OUT_ELEMS, nmock, 1.0f / (float)L_SEQ);
}